// round 3
// baseline (speedup 1.0000x reference)
#include <cuda_runtime.h>
#include <math.h>

// WaterNetModel, fused chunk-parallel scan in a single persistent kernel.
// NT=1096 split into C=4 chunks of L=274. Device-wide spin barrier between
// phases. Snow: max-plus recurrence s'=max(s+a, b) (composable).
// Bucket: h'=c*(h+xin), constant c (affine composable).
// Outputs: Q [NT,NS] | H [NT,NS,NH] | S [NT,NS,NH].

#define NT 1096
#define NS 2048
#define NH 16
#define C  4
#define L  274                 // NT / C
#define LANES (NS * NH)        // 32768
#define NTHREADS (C * LANES)   // 131072
#define BLK 256
#define NBLOCKS (NTHREADS / BLK)  // 512

// scratch (no cudaMalloc allowed)
__device__ float g_A[NTHREADS];       // snow compose slope offset
__device__ float g_B[NTHREADS];       // snow compose floor
__device__ float g_sstart[NTHREADS];  // chunk-start snow state
__device__ float g_D[NTHREADS];       // bucket chunk offset
__device__ float g_hstart[NTHREADS];  // chunk-start bucket state

// grid barrier state (g_gen monotonic across graph replays -> deterministic)
__device__ unsigned g_bar = 0;
__device__ unsigned g_gen = 0;

__device__ __forceinline__ void grid_sync()
{
    __syncthreads();
    if (threadIdx.x == 0) {
        __threadfence();  // publish this block's stores
        unsigned gen = *(volatile unsigned*)&g_gen;
        unsigned arr = atomicAdd(&g_bar, 1u);
        if (arr == (unsigned)gridDim.x - 1u) {
            g_bar = 0;
            __threadfence();
            *(volatile unsigned*)&g_gen = gen + 1u;
        } else {
            while (*(volatile unsigned*)&g_gen == gen) { __nanosleep(32); }
        }
        __threadfence();  // acquire others' stores
    }
    __syncthreads();
}

__global__ __launch_bounds__(BLK, 4)
void waternet_fused(const float* __restrict__ P, const float* __restrict__ T,
                    const float* __restrict__ w_i, const float* __restrict__ w_o,
                    const float* __restrict__ w_l, const float* __restrict__ w_s,
                    float* __restrict__ Q, float* __restrict__ H,
                    float* __restrict__ S)
{
    const int g     = blockIdx.x * BLK + threadIdx.x;  // [0, NTHREADS)
    const int lane  = g & (LANES - 1);
    const int chunk = g >> 15;
    const int h     = lane & (NH - 1);
    const int site  = lane >> 4;

    // time-invariant gate factors
    const float melt = expf(w_s[h]) + 1.0f;
    const float gi   = 1.0f / (1.0f + expf(-w_i[h]));
    const float gl   = 1.0f / (1.0f + expf(-w_l[h]));
    const float c1   = 1.0f - gl;

    const int t0 = chunk * L;
    const float* Pp = P + site;
    const float* Tp = T + site;

    // ---------------- Phase A: per-chunk snow composition (A, B) ----------
    {
        float A = 0.0f;
        float B = -INFINITY;
        #pragma unroll 4
        for (int k = 0; k < L; k++) {
            const float Tk = __ldg(Tp + (t0 + k) * NS);
            const float Pk = __ldg(Pp + (t0 + k) * NS);
            const float sm   = fmaxf(Tk, 0.0f) * melt;
            const float pneg = (Tk < 0.0f) ? Pk : 0.0f;
            const float a = pneg - sm;
            A += a;
            B = fmaxf(B + a, pneg);
        }
        g_A[g] = A;
        g_B[g] = B;
    }
    grid_sync();

    // ---------------- Phase B: chunk-start snow states --------------------
    if (g < LANES) {
        float s = 0.0f;
        #pragma unroll
        for (int c = 0; c < C; c++) {
            const int i = c * LANES + g;
            g_sstart[i] = s;
            s = fmaxf(s + g_A[i], g_B[i]);
        }
    }
    grid_sync();

    // ---------------- Phase C: replay snow, write S, accumulate D ---------
    {
        float s = g_sstart[g];
        float D = 0.0f;
        #pragma unroll 4
        for (int k = 0; k < L; k++) {
            const int t = t0 + k;
            const float Tk = __ldg(Tp + t * NS);
            const float Pk = __ldg(Pp + t * NS);
            const float sm   = fmaxf(Tk, 0.0f) * melt;
            const float m    = fminf(sm, s);
            const float pneg = (Tk < 0.0f) ? Pk : 0.0f;
            const float ppos = (Tk > 0.0f) ? Pk : 0.0f;
            const float sn   = s - m + pneg;
            const float xin  = (ppos + m) * gi;
            D = c1 * (D + xin);
            S[t * LANES + lane] = sn;
            s = sn;
        }
        g_D[g] = D;
    }
    grid_sync();

    // ---------------- Phase D: chunk-start bucket states ------------------
    if (g < LANES) {
        const float cL = powf(c1, (float)L);
        float hh = 0.0f;
        #pragma unroll
        for (int c = 0; c < C; c++) {
            const int i = c * LANES + g;
            g_hstart[i] = hh;
            hh = cL * hh + g_D[i];
        }
    }
    grid_sync();

    // ---------------- Phase E: replay full model, write H and Q -----------
    {
        // softmax over w_o
        float mx = w_o[0];
        #pragma unroll
        for (int j = 1; j < NH; j++) mx = fmaxf(mx, w_o[j]);
        float ssum = 0.0f;
        #pragma unroll
        for (int j = 0; j < NH; j++) ssum += expf(w_o[j] - mx);
        const float a = expf(w_o[h] - mx) / ssum;

        float s  = g_sstart[g];
        float hh = g_hstart[g];
        #pragma unroll 4
        for (int k = 0; k < L; k++) {
            const int t = t0 + k;
            const float Tk = __ldg(Tp + t * NS);
            const float Pk = __ldg(Pp + t * NS);
            const float sm   = fmaxf(Tk, 0.0f) * melt;
            const float m    = fminf(sm, s);
            const float pneg = (Tk < 0.0f) ? Pk : 0.0f;
            const float ppos = (Tk > 0.0f) ? Pk : 0.0f;
            const float sn   = s - m + pneg;
            const float xin  = (ppos + m) * gi;
            const float u    = xin + hh;
            const float q    = u * gl;
            const float hn   = u - q;

            H[t * LANES + lane] = hn;
            s  = sn;
            hh = hn;

            float qa = q * a;
            qa += __shfl_xor_sync(0xFFFFFFFFu, qa, 1);
            qa += __shfl_xor_sync(0xFFFFFFFFu, qa, 2);
            qa += __shfl_xor_sync(0xFFFFFFFFu, qa, 4);
            qa += __shfl_xor_sync(0xFFFFFFFFu, qa, 8);
            if (h == 0) Q[t * NS + site] = qa;
        }
    }
}

extern "C" void kernel_launch(void* const* d_in, const int* in_sizes, int n_in,
                              void* d_out, int out_size)
{
    const float* P   = (const float*)d_in[0];
    const float* T   = (const float*)d_in[1];
    const float* w_i = (const float*)d_in[2];
    const float* w_o = (const float*)d_in[3];
    const float* w_l = (const float*)d_in[4];
    const float* w_s = (const float*)d_in[5];

    float* Q = (float*)d_out;
    float* H = Q + (size_t)NT * NS;
    float* S = H + (size_t)NT * NS * NH;

    waternet_fused<<<NBLOCKS, BLK>>>(P, T, w_i, w_o, w_l, w_s, Q, H, S);
}

// round 4
// speedup vs baseline: 1.6544x; 1.6544x over previous
#include <cuda_runtime.h>
#include <math.h>

// WaterNetModel: chunk-parallel scan, fused persistent kernel, 4-bucket
// vectorization (one thread owns 4 of the 16 buckets of a site; states in
// registers; S/H written via STG.128).
// Snow: s' = max(s + a, b) (max-plus, composable).
// Bucket: h' = c*(h + xin), constant c (affine, composable).
// Outputs: Q [NT,NS] | H [NT,NS,NH] | S [NT,NS,NH].

#define NT 1096
#define NS 2048
#define NH 16
#define C  16
#define LFULL 69               // chunks 0..14
#define LLAST 61               // chunk 15: 1096 - 15*69
#define LANES (NS * NH)        // 32768
#define L4    (LANES / 4)      // 8192 vector lanes
#define NTHREADS (C * L4)      // 131072
#define BLK 256
#define NBLOCKS (NTHREADS / BLK)  // 512

// scratch (float4 per vector-lane per chunk)
__device__ float4 g_A[C * L4];
__device__ float4 g_B[C * L4];
__device__ float4 g_sstart[C * L4];
__device__ float4 g_D[C * L4];
__device__ float4 g_hstart[C * L4];

// grid barrier (generation counter; monotonic across graph replays)
__device__ unsigned g_bar = 0;
__device__ unsigned g_gen = 0;

__device__ __forceinline__ void grid_sync()
{
    __syncthreads();
    if (threadIdx.x == 0) {
        __threadfence();
        unsigned gen = *(volatile unsigned*)&g_gen;
        unsigned arr = atomicAdd(&g_bar, 1u);
        if (arr == (unsigned)gridDim.x - 1u) {
            g_bar = 0;
            __threadfence();
            *(volatile unsigned*)&g_gen = gen + 1u;
        } else {
            while (*(volatile unsigned*)&g_gen == gen) { __nanosleep(32); }
        }
        __threadfence();
    }
    __syncthreads();
}

__global__ __launch_bounds__(BLK, 4)
void waternet_fused(const float* __restrict__ P, const float* __restrict__ T,
                    const float* __restrict__ w_i, const float* __restrict__ w_o,
                    const float* __restrict__ w_l, const float* __restrict__ w_s,
                    float* __restrict__ Q, float* __restrict__ H,
                    float* __restrict__ S)
{
    const int g      = blockIdx.x * BLK + threadIdx.x;  // [0, NTHREADS)
    const int lane4  = g & (L4 - 1);                    // vector lane
    const int chunk  = g >> 13;                         // g / L4
    const int site   = lane4 >> 2;
    const int bg     = lane4 & 3;                       // bucket group (4 buckets)
    const int b0     = bg * 4;

    const int t0  = chunk * LFULL;
    const int len = (chunk == C - 1) ? LLAST : LFULL;

    // ---- per-bucket time-invariant factors (4 buckets) ----
    float melt[4], gi[4], gl[4], c1[4];
    #pragma unroll
    for (int j = 0; j < 4; j++) {
        melt[j] = expf(w_s[b0 + j]) + 1.0f;
        gi[j]   = 1.0f / (1.0f + expf(-w_i[b0 + j]));
        gl[j]   = 1.0f / (1.0f + expf(-w_l[b0 + j]));
        c1[j]   = 1.0f - gl[j];
    }

    const float* Pp = P + site;
    const float* Tp = T + site;

    // =============== Phase A: per-chunk snow composition ===============
    {
        float A[4] = {0, 0, 0, 0};
        float B[4] = {-INFINITY, -INFINITY, -INFINITY, -INFINITY};
        float pk = __ldg(Pp + t0 * NS);
        float tk = __ldg(Tp + t0 * NS);
        #pragma unroll 2
        for (int k = 0; k < len; k++) {
            float pn = 0.0f, tn = 0.0f;
            if (k + 1 < len) {
                pn = __ldg(Pp + (t0 + k + 1) * NS);
                tn = __ldg(Tp + (t0 + k + 1) * NS);
            }
            const float tpos = fmaxf(tk, 0.0f);
            const float pneg = (tk < 0.0f) ? pk : 0.0f;
            #pragma unroll
            for (int j = 0; j < 4; j++) {
                const float a = pneg - tpos * melt[j];
                A[j] += a;
                B[j] = fmaxf(B[j] + a, pneg);
            }
            pk = pn; tk = tn;
        }
        g_A[g] = make_float4(A[0], A[1], A[2], A[3]);
        g_B[g] = make_float4(B[0], B[1], B[2], B[3]);
    }
    grid_sync();

    // =============== Phase B: chunk-start snow states (tiny) ===========
    if (g < L4) {
        float s[4] = {0, 0, 0, 0};
        #pragma unroll
        for (int c = 0; c < C; c++) {
            const int i = c * L4 + g;
            g_sstart[i] = make_float4(s[0], s[1], s[2], s[3]);
            const float4 A = g_A[i];
            const float4 B = g_B[i];
            s[0] = fmaxf(s[0] + A.x, B.x);
            s[1] = fmaxf(s[1] + A.y, B.y);
            s[2] = fmaxf(s[2] + A.z, B.z);
            s[3] = fmaxf(s[3] + A.w, B.w);
        }
    }
    grid_sync();

    // =============== Phase C: replay snow, write S, accumulate D =======
    {
        const float4 s0 = g_sstart[g];
        float s[4] = {s0.x, s0.y, s0.z, s0.w};
        float D[4] = {0, 0, 0, 0};
        float4* S4 = (float4*)S + (size_t)t0 * L4 + lane4;

        float pk = __ldg(Pp + t0 * NS);
        float tk = __ldg(Tp + t0 * NS);
        #pragma unroll 2
        for (int k = 0; k < len; k++) {
            float pn = 0.0f, tn = 0.0f;
            if (k + 1 < len) {
                pn = __ldg(Pp + (t0 + k + 1) * NS);
                tn = __ldg(Tp + (t0 + k + 1) * NS);
            }
            const float tpos = fmaxf(tk, 0.0f);
            const float pneg = (tk < 0.0f) ? pk : 0.0f;
            const float ppos = (tk > 0.0f) ? pk : 0.0f;
            float sn[4];
            #pragma unroll
            for (int j = 0; j < 4; j++) {
                const float sm  = tpos * melt[j];
                const float m   = fminf(sm, s[j]);
                sn[j] = s[j] - m + pneg;
                const float xin = (ppos + m) * gi[j];
                D[j] = c1[j] * (D[j] + xin);
                s[j] = sn[j];
            }
            S4[(size_t)k * L4] = make_float4(sn[0], sn[1], sn[2], sn[3]);
            pk = pn; tk = tn;
        }
        g_D[g] = make_float4(D[0], D[1], D[2], D[3]);
    }
    grid_sync();

    // =============== Phase D: chunk-start bucket states (tiny) =========
    if (g < L4) {
        float cc[4], cLf[4], cLl[4];
        const int bb = (g & 3) * 4;
        #pragma unroll
        for (int j = 0; j < 4; j++) {
            cc[j]  = 1.0f - 1.0f / (1.0f + expf(-w_l[bb + j]));
            cLf[j] = powf(cc[j], (float)LFULL);
            cLl[j] = powf(cc[j], (float)LLAST);
        }
        float hh[4] = {0, 0, 0, 0};
        #pragma unroll
        for (int c = 0; c < C; c++) {
            const int i = c * L4 + g;
            g_hstart[i] = make_float4(hh[0], hh[1], hh[2], hh[3]);
            const float4 D = g_D[i];
            const float* cL = (c == C - 1) ? cLl : cLf;
            hh[0] = cL[0] * hh[0] + D.x;
            hh[1] = cL[1] * hh[1] + D.y;
            hh[2] = cL[2] * hh[2] + D.z;
            hh[3] = cL[3] * hh[3] + D.w;
        }
    }
    grid_sync();

    // =============== Phase E: full replay, write H and Q ===============
    {
        // softmax over w_o; keep this thread's 4 weights
        float mx = w_o[0];
        #pragma unroll
        for (int j = 1; j < NH; j++) mx = fmaxf(mx, w_o[j]);
        float ssum = 0.0f;
        #pragma unroll
        for (int j = 0; j < NH; j++) ssum += expf(w_o[j] - mx);
        float aw[4];
        #pragma unroll
        for (int j = 0; j < 4; j++) aw[j] = expf(w_o[b0 + j] - mx) / ssum;

        const float4 s0 = g_sstart[g];
        const float4 h0 = g_hstart[g];
        float s[4]  = {s0.x, s0.y, s0.z, s0.w};
        float hh[4] = {h0.x, h0.y, h0.z, h0.w};
        float4* H4 = (float4*)H + (size_t)t0 * L4 + lane4;

        float pk = __ldg(Pp + t0 * NS);
        float tk = __ldg(Tp + t0 * NS);
        #pragma unroll 2
        for (int k = 0; k < len; k++) {
            float pn = 0.0f, tn = 0.0f;
            if (k + 1 < len) {
                pn = __ldg(Pp + (t0 + k + 1) * NS);
                tn = __ldg(Tp + (t0 + k + 1) * NS);
            }
            const float tpos = fmaxf(tk, 0.0f);
            const float pneg = (tk < 0.0f) ? pk : 0.0f;
            const float ppos = (tk > 0.0f) ? pk : 0.0f;
            float hn[4];
            float qa = 0.0f;
            #pragma unroll
            for (int j = 0; j < 4; j++) {
                const float sm  = tpos * melt[j];
                const float m   = fminf(sm, s[j]);
                s[j] = s[j] - m + pneg;
                const float xin = (ppos + m) * gi[j];
                const float u   = xin + hh[j];
                const float q   = u * gl[j];
                hn[j] = u - q;
                hh[j] = hn[j];
                qa = fmaf(q, aw[j], qa);
            }
            H4[(size_t)k * L4] = make_float4(hn[0], hn[1], hn[2], hn[3]);

            // reduce over the 4 threads of this site
            qa += __shfl_xor_sync(0xFFFFFFFFu, qa, 1);
            qa += __shfl_xor_sync(0xFFFFFFFFu, qa, 2);
            if (bg == 0) Q[(t0 + k) * NS + site] = qa;

            pk = pn; tk = tn;
        }
    }
}

extern "C" void kernel_launch(void* const* d_in, const int* in_sizes, int n_in,
                              void* d_out, int out_size)
{
    const float* P   = (const float*)d_in[0];
    const float* T   = (const float*)d_in[1];
    const float* w_i = (const float*)d_in[2];
    const float* w_o = (const float*)d_in[3];
    const float* w_l = (const float*)d_in[4];
    const float* w_s = (const float*)d_in[5];

    float* Q = (float*)d_out;
    float* H = Q + (size_t)NT * NS;
    float* S = H + (size_t)NT * NS * NH;

    waternet_fused<<<NBLOCKS, BLK>>>(P, T, w_i, w_o, w_l, w_s, Q, H, S);
}

// round 5
// speedup vs baseline: 2.0236x; 1.2231x over previous
#include <cuda_runtime.h>
#include <math.h>

// WaterNetModel: chunk-parallel scan, fused persistent kernel, 4-bucket
// vectorization. Round 5: BLK=128 -> 1024 blocks (8 CTAs/SM) to fix the
// 512-block placement imbalance (68 SMs had 4 CTAs, 80 had 3).
// Snow: s' = max(s + a, b) (max-plus, composable).
// Bucket: h' = c*(h + xin), constant c (affine, composable).
// Outputs: Q [NT,NS] | H [NT,NS,NH] | S [NT,NS,NH].

#define NT 1096
#define NS 2048
#define NH 16
#define C  16
#define LFULL 69               // chunks 0..14
#define LLAST 61               // chunk 15: 1096 - 15*69
#define LANES (NS * NH)        // 32768
#define L4    (LANES / 4)      // 8192 vector lanes
#define NTHREADS (C * L4)      // 131072
#define BLK 128
#define NBLOCKS (NTHREADS / BLK)  // 1024  (<= 8*148 = 1184 resident slots)

// scratch (float4 per vector-lane per chunk)
__device__ float4 g_A[C * L4];
__device__ float4 g_B[C * L4];
__device__ float4 g_sstart[C * L4];
__device__ float4 g_D[C * L4];
__device__ float4 g_hstart[C * L4];

// grid barrier (generation counter; monotonic across graph replays)
__device__ unsigned g_bar = 0;
__device__ unsigned g_gen = 0;

__device__ __forceinline__ void grid_sync()
{
    __syncthreads();
    if (threadIdx.x == 0) {
        __threadfence();
        unsigned gen = *(volatile unsigned*)&g_gen;
        unsigned arr = atomicAdd(&g_bar, 1u);
        if (arr == (unsigned)gridDim.x - 1u) {
            g_bar = 0;
            __threadfence();
            *(volatile unsigned*)&g_gen = gen + 1u;
        } else {
            while (*(volatile unsigned*)&g_gen == gen) { __nanosleep(32); }
        }
        __threadfence();
    }
    __syncthreads();
}

__global__ __launch_bounds__(BLK, 8)
void waternet_fused(const float* __restrict__ P, const float* __restrict__ T,
                    const float* __restrict__ w_i, const float* __restrict__ w_o,
                    const float* __restrict__ w_l, const float* __restrict__ w_s,
                    float* __restrict__ Q, float* __restrict__ H,
                    float* __restrict__ S)
{
    const int g      = blockIdx.x * BLK + threadIdx.x;  // [0, NTHREADS)
    const int lane4  = g & (L4 - 1);                    // vector lane
    const int chunk  = g >> 13;                         // g / L4
    const int site   = lane4 >> 2;
    const int bg     = lane4 & 3;                       // bucket group
    const int b0     = bg * 4;

    const int t0  = chunk * LFULL;
    const int len = (chunk == C - 1) ? LLAST : LFULL;

    // ---- per-bucket time-invariant factors (4 buckets) ----
    float melt[4], gi[4], gl[4], c1[4];
    #pragma unroll
    for (int j = 0; j < 4; j++) {
        melt[j] = expf(w_s[b0 + j]) + 1.0f;
        gi[j]   = 1.0f / (1.0f + expf(-w_i[b0 + j]));
        gl[j]   = 1.0f / (1.0f + expf(-w_l[b0 + j]));
        c1[j]   = 1.0f - gl[j];
    }

    const float* Pp = P + site;
    const float* Tp = T + site;

    // =============== Phase A: per-chunk snow composition ===============
    {
        float A[4] = {0, 0, 0, 0};
        float B[4] = {-INFINITY, -INFINITY, -INFINITY, -INFINITY};
        float pk = __ldg(Pp + t0 * NS);
        float tk = __ldg(Tp + t0 * NS);
        #pragma unroll 4
        for (int k = 0; k < len; k++) {
            float pn = 0.0f, tn = 0.0f;
            if (k + 1 < len) {
                pn = __ldg(Pp + (t0 + k + 1) * NS);
                tn = __ldg(Tp + (t0 + k + 1) * NS);
            }
            const float tpos = fmaxf(tk, 0.0f);
            const float pneg = (tk < 0.0f) ? pk : 0.0f;
            #pragma unroll
            for (int j = 0; j < 4; j++) {
                const float a = pneg - tpos * melt[j];
                A[j] += a;
                B[j] = fmaxf(B[j] + a, pneg);
            }
            pk = pn; tk = tn;
        }
        g_A[g] = make_float4(A[0], A[1], A[2], A[3]);
        g_B[g] = make_float4(B[0], B[1], B[2], B[3]);
    }
    grid_sync();

    // =============== Phase B: chunk-start snow states (tiny) ===========
    if (g < L4) {
        float s[4] = {0, 0, 0, 0};
        #pragma unroll
        for (int c = 0; c < C; c++) {
            const int i = c * L4 + g;
            g_sstart[i] = make_float4(s[0], s[1], s[2], s[3]);
            const float4 A = g_A[i];
            const float4 B = g_B[i];
            s[0] = fmaxf(s[0] + A.x, B.x);
            s[1] = fmaxf(s[1] + A.y, B.y);
            s[2] = fmaxf(s[2] + A.z, B.z);
            s[3] = fmaxf(s[3] + A.w, B.w);
        }
    }
    grid_sync();

    // =============== Phase C: replay snow, write S, accumulate D =======
    {
        const float4 s0 = g_sstart[g];
        float s[4] = {s0.x, s0.y, s0.z, s0.w};
        float D[4] = {0, 0, 0, 0};
        float4* S4 = (float4*)S + (size_t)t0 * L4 + lane4;

        float pk = __ldg(Pp + t0 * NS);
        float tk = __ldg(Tp + t0 * NS);
        #pragma unroll 4
        for (int k = 0; k < len; k++) {
            float pn = 0.0f, tn = 0.0f;
            if (k + 1 < len) {
                pn = __ldg(Pp + (t0 + k + 1) * NS);
                tn = __ldg(Tp + (t0 + k + 1) * NS);
            }
            const float tpos = fmaxf(tk, 0.0f);
            const float pneg = (tk < 0.0f) ? pk : 0.0f;
            const float ppos = (tk > 0.0f) ? pk : 0.0f;
            float sn[4];
            #pragma unroll
            for (int j = 0; j < 4; j++) {
                const float sm  = tpos * melt[j];
                const float m   = fminf(sm, s[j]);
                sn[j] = s[j] - m + pneg;
                const float xin = (ppos + m) * gi[j];
                D[j] = c1[j] * (D[j] + xin);
                s[j] = sn[j];
            }
            S4[(size_t)k * L4] = make_float4(sn[0], sn[1], sn[2], sn[3]);
            pk = pn; tk = tn;
        }
        g_D[g] = make_float4(D[0], D[1], D[2], D[3]);
    }
    grid_sync();

    // =============== Phase D: chunk-start bucket states (tiny) =========
    if (g < L4) {
        float cc[4], cLf[4], cLl[4];
        const int bb = (g & 3) * 4;
        #pragma unroll
        for (int j = 0; j < 4; j++) {
            cc[j]  = 1.0f - 1.0f / (1.0f + expf(-w_l[bb + j]));
            cLf[j] = powf(cc[j], (float)LFULL);
            cLl[j] = powf(cc[j], (float)LLAST);
        }
        float hh[4] = {0, 0, 0, 0};
        #pragma unroll
        for (int c = 0; c < C; c++) {
            const int i = c * L4 + g;
            g_hstart[i] = make_float4(hh[0], hh[1], hh[2], hh[3]);
            const float4 D = g_D[i];
            const float* cL = (c == C - 1) ? cLl : cLf;
            hh[0] = cL[0] * hh[0] + D.x;
            hh[1] = cL[1] * hh[1] + D.y;
            hh[2] = cL[2] * hh[2] + D.z;
            hh[3] = cL[3] * hh[3] + D.w;
        }
    }
    grid_sync();

    // =============== Phase E: full replay, write H and Q ===============
    {
        // softmax over w_o; keep this thread's 4 weights
        float mx = w_o[0];
        #pragma unroll
        for (int j = 1; j < NH; j++) mx = fmaxf(mx, w_o[j]);
        float ssum = 0.0f;
        #pragma unroll
        for (int j = 0; j < NH; j++) ssum += expf(w_o[j] - mx);
        float aw[4];
        #pragma unroll
        for (int j = 0; j < 4; j++) aw[j] = expf(w_o[b0 + j] - mx) / ssum;

        const float4 s0 = g_sstart[g];
        const float4 h0 = g_hstart[g];
        float s[4]  = {s0.x, s0.y, s0.z, s0.w};
        float hh[4] = {h0.x, h0.y, h0.z, h0.w};
        float4* H4 = (float4*)H + (size_t)t0 * L4 + lane4;

        float pk = __ldg(Pp + t0 * NS);
        float tk = __ldg(Tp + t0 * NS);
        #pragma unroll 4
        for (int k = 0; k < len; k++) {
            float pn = 0.0f, tn = 0.0f;
            if (k + 1 < len) {
                pn = __ldg(Pp + (t0 + k + 1) * NS);
                tn = __ldg(Tp + (t0 + k + 1) * NS);
            }
            const float tpos = fmaxf(tk, 0.0f);
            const float pneg = (tk < 0.0f) ? pk : 0.0f;
            const float ppos = (tk > 0.0f) ? pk : 0.0f;
            float hn[4];
            float qa = 0.0f;
            #pragma unroll
            for (int j = 0; j < 4; j++) {
                const float sm  = tpos * melt[j];
                const float m   = fminf(sm, s[j]);
                s[j] = s[j] - m + pneg;
                const float xin = (ppos + m) * gi[j];
                const float u   = xin + hh[j];
                const float q   = u * gl[j];
                hn[j] = u - q;
                hh[j] = hn[j];
                qa = fmaf(q, aw[j], qa);
            }
            H4[(size_t)k * L4] = make_float4(hn[0], hn[1], hn[2], hn[3]);

            // reduce over the 4 threads of this site
            qa += __shfl_xor_sync(0xFFFFFFFFu, qa, 1);
            qa += __shfl_xor_sync(0xFFFFFFFFu, qa, 2);
            if (bg == 0) Q[(t0 + k) * NS + site] = qa;

            pk = pn; tk = tn;
        }
    }
}

extern "C" void kernel_launch(void* const* d_in, const int* in_sizes, int n_in,
                              void* d_out, int out_size)
{
    const float* P   = (const float*)d_in[0];
    const float* T   = (const float*)d_in[1];
    const float* w_i = (const float*)d_in[2];
    const float* w_o = (const float*)d_in[3];
    const float* w_l = (const float*)d_in[4];
    const float* w_s = (const float*)d_in[5];

    float* Q = (float*)d_out;
    float* H = Q + (size_t)NT * NS;
    float* S = H + (size_t)NT * NS * NH;

    waternet_fused<<<NBLOCKS, BLK>>>(P, T, w_i, w_o, w_l, w_s, Q, H, S);
}

// round 6
// speedup vs baseline: 2.4797x; 1.2254x over previous
#include <cuda_runtime.h>
#include <math.h>

// WaterNetModel: chunk-parallel scan, fused persistent kernel, 4-bucket
// vectorization. Round 6: group-of-4 software pipeline on P/T loads (MLP ~8),
// streaming stores for S/H/Q (keep P/T L2-resident), chunks sized /4.
// Snow: s' = max(s + a, b) (max-plus, composable).
// Bucket: h' = c*(h + xin), constant c (affine, composable).
// Outputs: Q [NT,NS] | H [NT,NS,NH] | S [NT,NS,NH].

#define NT 1096
#define NS 2048
#define NH 16
#define C  16
#define LF 68                  // chunks 0..14 (17 groups of 4)
#define LL 76                  // chunk 15     (19 groups of 4)
#define LANES (NS * NH)        // 32768
#define L4    (LANES / 4)      // 8192 vector lanes
#define NTHREADS (C * L4)      // 131072
#define BLK 128
#define NBLOCKS (NTHREADS / BLK)  // 1024 (<= 8*148 resident slots)

__device__ float4 g_A[C * L4];
__device__ float4 g_B[C * L4];
__device__ float4 g_sstart[C * L4];
__device__ float4 g_D[C * L4];
__device__ float4 g_hstart[C * L4];

__device__ unsigned g_bar = 0;
__device__ unsigned g_gen = 0;

__device__ __forceinline__ void grid_sync()
{
    __syncthreads();
    if (threadIdx.x == 0) {
        __threadfence();
        unsigned gen = *(volatile unsigned*)&g_gen;
        unsigned arr = atomicAdd(&g_bar, 1u);
        if (arr == (unsigned)gridDim.x - 1u) {
            g_bar = 0;
            __threadfence();
            *(volatile unsigned*)&g_gen = gen + 1u;
        } else {
            while (*(volatile unsigned*)&g_gen == gen) { __nanosleep(32); }
        }
        __threadfence();
    }
    __syncthreads();
}

__global__ __launch_bounds__(BLK, 8)
void waternet_fused(const float* __restrict__ P, const float* __restrict__ T,
                    const float* __restrict__ w_i, const float* __restrict__ w_o,
                    const float* __restrict__ w_l, const float* __restrict__ w_s,
                    float* __restrict__ Q, float* __restrict__ H,
                    float* __restrict__ S)
{
    const int g      = blockIdx.x * BLK + threadIdx.x;  // [0, NTHREADS)
    const int lane4  = g & (L4 - 1);
    const int chunk  = g >> 13;
    const int site   = lane4 >> 2;
    const int bg     = lane4 & 3;
    const int b0     = bg * 4;

    const int t0  = chunk * LF;
    const int len = (chunk == C - 1) ? LL : LF;
    const int nG  = len >> 2;                  // groups of 4

    float melt[4], gi[4], gl[4], c1[4];
    #pragma unroll
    for (int j = 0; j < 4; j++) {
        melt[j] = expf(w_s[b0 + j]) + 1.0f;
        gi[j]   = 1.0f / (1.0f + expf(-w_i[b0 + j]));
        gl[j]   = 1.0f / (1.0f + expf(-w_l[b0 + j]));
        c1[j]   = 1.0f - gl[j];
    }

    const float* Pp = P + site;
    const float* Tp = T + site;

    // =============== Phase A: per-chunk snow composition ===============
    {
        float A[4] = {0, 0, 0, 0};
        float B[4] = {-INFINITY, -INFINITY, -INFINITY, -INFINITY};

        float pa[4], ta[4];
        #pragma unroll
        for (int j = 0; j < 4; j++) {
            pa[j] = __ldg(Pp + (t0 + j) * NS);
            ta[j] = __ldg(Tp + (t0 + j) * NS);
        }
        for (int g0 = 0; g0 < nG; g0++) {
            float pb[4], tb[4];
            const int kn = (g0 + 1 < nG) ? (g0 + 1) * 4 : (len - 4);
            #pragma unroll
            for (int j = 0; j < 4; j++) {
                pb[j] = __ldg(Pp + (t0 + kn + j) * NS);
                tb[j] = __ldg(Tp + (t0 + kn + j) * NS);
            }
            #pragma unroll
            for (int u = 0; u < 4; u++) {
                const float tpos = fmaxf(ta[u], 0.0f);
                const float pneg = (ta[u] < 0.0f) ? pa[u] : 0.0f;
                #pragma unroll
                for (int j = 0; j < 4; j++) {
                    const float a = pneg - tpos * melt[j];
                    A[j] += a;
                    B[j] = fmaxf(B[j] + a, pneg);
                }
            }
            #pragma unroll
            for (int j = 0; j < 4; j++) { pa[j] = pb[j]; ta[j] = tb[j]; }
        }
        g_A[g] = make_float4(A[0], A[1], A[2], A[3]);
        g_B[g] = make_float4(B[0], B[1], B[2], B[3]);
    }
    grid_sync();

    // =============== Phase B: chunk-start snow states ==================
    if (g < L4) {
        float s[4] = {0, 0, 0, 0};
        #pragma unroll
        for (int c = 0; c < C; c++) {
            const int i = c * L4 + g;
            g_sstart[i] = make_float4(s[0], s[1], s[2], s[3]);
            const float4 A = g_A[i];
            const float4 B = g_B[i];
            s[0] = fmaxf(s[0] + A.x, B.x);
            s[1] = fmaxf(s[1] + A.y, B.y);
            s[2] = fmaxf(s[2] + A.z, B.z);
            s[3] = fmaxf(s[3] + A.w, B.w);
        }
    }
    grid_sync();

    // =============== Phase C: replay snow, write S, accumulate D =======
    {
        const float4 s0 = g_sstart[g];
        float s[4] = {s0.x, s0.y, s0.z, s0.w};
        float D[4] = {0, 0, 0, 0};
        float4* S4 = (float4*)S + (size_t)t0 * L4 + lane4;

        float pa[4], ta[4];
        #pragma unroll
        for (int j = 0; j < 4; j++) {
            pa[j] = __ldg(Pp + (t0 + j) * NS);
            ta[j] = __ldg(Tp + (t0 + j) * NS);
        }
        for (int g0 = 0; g0 < nG; g0++) {
            float pb[4], tb[4];
            const int kn = (g0 + 1 < nG) ? (g0 + 1) * 4 : (len - 4);
            #pragma unroll
            for (int j = 0; j < 4; j++) {
                pb[j] = __ldg(Pp + (t0 + kn + j) * NS);
                tb[j] = __ldg(Tp + (t0 + kn + j) * NS);
            }
            #pragma unroll
            for (int u = 0; u < 4; u++) {
                const int k = g0 * 4 + u;
                const float tpos = fmaxf(ta[u], 0.0f);
                const float pneg = (ta[u] < 0.0f) ? pa[u] : 0.0f;
                const float ppos = (ta[u] > 0.0f) ? pa[u] : 0.0f;
                float sn[4];
                #pragma unroll
                for (int j = 0; j < 4; j++) {
                    const float sm  = tpos * melt[j];
                    const float m   = fminf(sm, s[j]);
                    sn[j] = s[j] - m + pneg;
                    const float xin = (ppos + m) * gi[j];
                    D[j] = c1[j] * (D[j] + xin);
                    s[j] = sn[j];
                }
                __stcs(&S4[(size_t)k * L4], make_float4(sn[0], sn[1], sn[2], sn[3]));
            }
            #pragma unroll
            for (int j = 0; j < 4; j++) { pa[j] = pb[j]; ta[j] = tb[j]; }
        }
        g_D[g] = make_float4(D[0], D[1], D[2], D[3]);
    }
    grid_sync();

    // =============== Phase D: chunk-start bucket states ================
    if (g < L4) {
        float cc[4], cLf[4], cLl[4];
        const int bb = (g & 3) * 4;
        #pragma unroll
        for (int j = 0; j < 4; j++) {
            cc[j]  = 1.0f - 1.0f / (1.0f + expf(-w_l[bb + j]));
            cLf[j] = powf(cc[j], (float)LF);
            cLl[j] = powf(cc[j], (float)LL);
        }
        float hh[4] = {0, 0, 0, 0};
        #pragma unroll
        for (int c = 0; c < C; c++) {
            const int i = c * L4 + g;
            g_hstart[i] = make_float4(hh[0], hh[1], hh[2], hh[3]);
            const float4 D = g_D[i];
            const float* cL = (c == C - 1) ? cLl : cLf;
            hh[0] = cL[0] * hh[0] + D.x;
            hh[1] = cL[1] * hh[1] + D.y;
            hh[2] = cL[2] * hh[2] + D.z;
            hh[3] = cL[3] * hh[3] + D.w;
        }
    }
    grid_sync();

    // =============== Phase E: full replay, write H and Q ===============
    {
        float mx = w_o[0];
        #pragma unroll
        for (int j = 1; j < NH; j++) mx = fmaxf(mx, w_o[j]);
        float ssum = 0.0f;
        #pragma unroll
        for (int j = 0; j < NH; j++) ssum += expf(w_o[j] - mx);
        float aw[4];
        #pragma unroll
        for (int j = 0; j < 4; j++) aw[j] = expf(w_o[b0 + j] - mx) / ssum;

        const float4 s0 = g_sstart[g];
        const float4 h0 = g_hstart[g];
        float s[4]  = {s0.x, s0.y, s0.z, s0.w};
        float hh[4] = {h0.x, h0.y, h0.z, h0.w};
        float4* H4 = (float4*)H + (size_t)t0 * L4 + lane4;

        float pa[4], ta[4];
        #pragma unroll
        for (int j = 0; j < 4; j++) {
            pa[j] = __ldg(Pp + (t0 + j) * NS);
            ta[j] = __ldg(Tp + (t0 + j) * NS);
        }
        for (int g0 = 0; g0 < nG; g0++) {
            float pb[4], tb[4];
            const int kn = (g0 + 1 < nG) ? (g0 + 1) * 4 : (len - 4);
            #pragma unroll
            for (int j = 0; j < 4; j++) {
                pb[j] = __ldg(Pp + (t0 + kn + j) * NS);
                tb[j] = __ldg(Tp + (t0 + kn + j) * NS);
            }
            #pragma unroll
            for (int u = 0; u < 4; u++) {
                const int k = g0 * 4 + u;
                const float tpos = fmaxf(ta[u], 0.0f);
                const float pneg = (ta[u] < 0.0f) ? pa[u] : 0.0f;
                const float ppos = (ta[u] > 0.0f) ? pa[u] : 0.0f;
                float hn[4];
                float qa = 0.0f;
                #pragma unroll
                for (int j = 0; j < 4; j++) {
                    const float sm  = tpos * melt[j];
                    const float m   = fminf(sm, s[j]);
                    s[j] = s[j] - m + pneg;
                    const float xin = (ppos + m) * gi[j];
                    const float u2  = xin + hh[j];
                    const float q   = u2 * gl[j];
                    hn[j] = u2 - q;
                    hh[j] = hn[j];
                    qa = fmaf(q, aw[j], qa);
                }
                __stcs(&H4[(size_t)k * L4], make_float4(hn[0], hn[1], hn[2], hn[3]));

                qa += __shfl_xor_sync(0xFFFFFFFFu, qa, 1);
                qa += __shfl_xor_sync(0xFFFFFFFFu, qa, 2);
                if (bg == 0) __stcs(&Q[(t0 + k) * NS + site], qa);
            }
            #pragma unroll
            for (int j = 0; j < 4; j++) { pa[j] = pb[j]; ta[j] = tb[j]; }
        }
    }
}

extern "C" void kernel_launch(void* const* d_in, const int* in_sizes, int n_in,
                              void* d_out, int out_size)
{
    const float* P   = (const float*)d_in[0];
    const float* T   = (const float*)d_in[1];
    const float* w_i = (const float*)d_in[2];
    const float* w_o = (const float*)d_in[3];
    const float* w_l = (const float*)d_in[4];
    const float* w_s = (const float*)d_in[5];

    float* Q = (float*)d_out;
    float* H = Q + (size_t)NT * NS;
    float* S = H + (size_t)NT * NS * NH;

    waternet_fused<<<NBLOCKS, BLK>>>(P, T, w_i, w_o, w_l, w_s, Q, H, S);
}

// round 7
// speedup vs baseline: 2.6650x; 1.0747x over previous
#include <cuda_runtime.h>
#include <math.h>

// WaterNetModel: chunk-parallel scan, fused persistent kernel.
// Round 7: phase A uses half-site threads (8 buckets/thread, 2x fewer LDGs),
// phase D inlined into phase E, 3 grid_syncs instead of 4.
// Snow: s' = max(s + a, b) (max-plus, composable).
// Bucket: h' = c*(h + xin), constant c (affine, composable).
// Outputs: Q [NT,NS] | H [NT,NS,NH] | S [NT,NS,NH].

#define NT 1096
#define NS 2048
#define NH 16
#define C16 16
#define LF 68                  // C-chunks 0..14
#define LL 76                  // C-chunk 15
#define CA 32                  // A-chunks (2 per C-chunk; 68=36+32, 76=40+36)
#define LANES (NS * NH)        // 32768
#define L4    (LANES / 4)      // 8192
#define NTHREADS (C16 * L4)    // 131072
#define BLK 128
#define NBLOCKS (NTHREADS / BLK)  // 1024 (8 CTAs/SM cap -> all resident)

// scratch
__device__ float g_A[CA * LANES];        // 4 MB  snow compose slope
__device__ float g_B[CA * LANES];        // 4 MB  snow compose floor
__device__ float g_sstart[C16 * LANES];  // 2 MB  C-chunk start snow state
__device__ float g_D[C16 * LANES];       // 2 MB  bucket chunk offsets

__device__ unsigned g_bar = 0;
__device__ unsigned g_gen = 0;

__device__ __forceinline__ void grid_sync()
{
    __syncthreads();
    if (threadIdx.x == 0) {
        __threadfence();
        unsigned gen = *(volatile unsigned*)&g_gen;
        unsigned arr = atomicAdd(&g_bar, 1u);
        if (arr == (unsigned)gridDim.x - 1u) {
            g_bar = 0;
            __threadfence();
            *(volatile unsigned*)&g_gen = gen + 1u;
        } else {
            while (*(volatile unsigned*)&g_gen == gen) { __nanosleep(32); }
        }
        __threadfence();
    }
    __syncthreads();
}

__global__ __launch_bounds__(BLK, 8)
void waternet_fused(const float* __restrict__ P, const float* __restrict__ T,
                    const float* __restrict__ w_i, const float* __restrict__ w_o,
                    const float* __restrict__ w_l, const float* __restrict__ w_s,
                    float* __restrict__ Q, float* __restrict__ H,
                    float* __restrict__ S)
{
    const int g = blockIdx.x * BLK + threadIdx.x;   // [0, NTHREADS)

    // =============== Phase A: snow composition, half-site threads =======
    {
        const int caA   = g >> 12;          // A-chunk [0,32)
        const int rem   = g & 4095;
        const int siteA = rem >> 1;
        const int half  = rem & 1;
        const int b0A   = half * 8;

        const int c16A = caA >> 1;
        int lenA, t0A;
        if (c16A < 15) {
            lenA = (caA & 1) ? 32 : 36;
            t0A  = 68 * c16A + ((caA & 1) ? 36 : 0);
        } else {
            lenA = (caA & 1) ? 36 : 40;
            t0A  = 1020 + ((caA & 1) ? 40 : 0);
        }
        const int nG = lenA >> 2;

        float meltA[8];
        #pragma unroll
        for (int j = 0; j < 8; j++) meltA[j] = expf(w_s[b0A + j]) + 1.0f;

        float A[8], B[8];
        #pragma unroll
        for (int j = 0; j < 8; j++) { A[j] = 0.0f; B[j] = -INFINITY; }

        const float* PpA = P + siteA;
        const float* TpA = T + siteA;

        float pa[4], ta[4];
        #pragma unroll
        for (int j = 0; j < 4; j++) {
            pa[j] = __ldg(PpA + (t0A + j) * NS);
            ta[j] = __ldg(TpA + (t0A + j) * NS);
        }
        for (int g0 = 0; g0 < nG; g0++) {
            float pb[4], tb[4];
            const int kn = (g0 + 1 < nG) ? (g0 + 1) * 4 : (lenA - 4);
            #pragma unroll
            for (int j = 0; j < 4; j++) {
                pb[j] = __ldg(PpA + (t0A + kn + j) * NS);
                tb[j] = __ldg(TpA + (t0A + kn + j) * NS);
            }
            #pragma unroll
            for (int u = 0; u < 4; u++) {
                const float tpos = fmaxf(ta[u], 0.0f);
                const float pneg = (ta[u] < 0.0f) ? pa[u] : 0.0f;
                #pragma unroll
                for (int j = 0; j < 8; j++) {
                    const float a = pneg - tpos * meltA[j];
                    A[j] += a;
                    B[j] = fmaxf(B[j] + a, pneg);
                }
            }
            #pragma unroll
            for (int j = 0; j < 4; j++) { pa[j] = pb[j]; ta[j] = tb[j]; }
        }

        float4* dA = (float4*)&g_A[caA * LANES + siteA * NH + b0A];
        float4* dB = (float4*)&g_B[caA * LANES + siteA * NH + b0A];
        dA[0] = make_float4(A[0], A[1], A[2], A[3]);
        dA[1] = make_float4(A[4], A[5], A[6], A[7]);
        dB[0] = make_float4(B[0], B[1], B[2], B[3]);
        dB[1] = make_float4(B[4], B[5], B[6], B[7]);
    }
    grid_sync();

    // =============== Phase B: chunk-start snow states (lane threads) ====
    if (g < LANES) {
        float s = 0.0f;
        #pragma unroll
        for (int ca = 0; ca < CA; ca++) {
            if ((ca & 1) == 0) g_sstart[(ca >> 1) * LANES + g] = s;
            s = fmaxf(s + g_A[ca * LANES + g], g_B[ca * LANES + g]);
        }
    }
    grid_sync();

    // ---- common decode for phases C and E (quad threads) ----
    const int lane4 = g & (L4 - 1);
    const int chunk = g >> 13;
    const int site  = lane4 >> 2;
    const int bg    = lane4 & 3;
    const int b0    = bg * 4;

    const int t0  = chunk * LF;
    const int len = (chunk == C16 - 1) ? LL : LF;
    const int nG  = len >> 2;

    float melt[4], gi[4], gl[4], c1[4];
    #pragma unroll
    for (int j = 0; j < 4; j++) {
        melt[j] = expf(w_s[b0 + j]) + 1.0f;
        gi[j]   = 1.0f / (1.0f + expf(-w_i[b0 + j]));
        gl[j]   = 1.0f / (1.0f + expf(-w_l[b0 + j]));
        c1[j]   = 1.0f - gl[j];
    }

    const float* Pp = P + site;
    const float* Tp = T + site;

    // =============== Phase C: replay snow, write S, accumulate D ========
    {
        const float4 s0 = ((const float4*)g_sstart)[chunk * L4 + lane4];
        float s[4] = {s0.x, s0.y, s0.z, s0.w};
        float D[4] = {0, 0, 0, 0};
        float4* S4 = (float4*)S + (size_t)t0 * L4 + lane4;

        float pa[4], ta[4];
        #pragma unroll
        for (int j = 0; j < 4; j++) {
            pa[j] = __ldg(Pp + (t0 + j) * NS);
            ta[j] = __ldg(Tp + (t0 + j) * NS);
        }
        for (int g0 = 0; g0 < nG; g0++) {
            float pb[4], tb[4];
            const int kn = (g0 + 1 < nG) ? (g0 + 1) * 4 : (len - 4);
            #pragma unroll
            for (int j = 0; j < 4; j++) {
                pb[j] = __ldg(Pp + (t0 + kn + j) * NS);
                tb[j] = __ldg(Tp + (t0 + kn + j) * NS);
            }
            #pragma unroll
            for (int u = 0; u < 4; u++) {
                const int k = g0 * 4 + u;
                const float tpos = fmaxf(ta[u], 0.0f);
                const float pneg = (ta[u] < 0.0f) ? pa[u] : 0.0f;
                const float ppos = (ta[u] > 0.0f) ? pa[u] : 0.0f;
                float sn[4];
                #pragma unroll
                for (int j = 0; j < 4; j++) {
                    const float sm  = tpos * melt[j];
                    const float m   = fminf(sm, s[j]);
                    sn[j] = s[j] - m + pneg;
                    const float xin = (ppos + m) * gi[j];
                    D[j] = c1[j] * (D[j] + xin);
                    s[j] = sn[j];
                }
                __stcs(&S4[(size_t)k * L4], make_float4(sn[0], sn[1], sn[2], sn[3]));
            }
            #pragma unroll
            for (int j = 0; j < 4; j++) { pa[j] = pb[j]; ta[j] = tb[j]; }
        }
        ((float4*)g_D)[chunk * L4 + lane4] = make_float4(D[0], D[1], D[2], D[3]);
    }
    grid_sync();

    // =============== Phase E: inline h_start, replay, write H and Q =====
    {
        float mx = w_o[0];
        #pragma unroll
        for (int j = 1; j < NH; j++) mx = fmaxf(mx, w_o[j]);
        float ssum = 0.0f;
        #pragma unroll
        for (int j = 0; j < NH; j++) ssum += expf(w_o[j] - mx);
        float aw[4];
        #pragma unroll
        for (int j = 0; j < 4; j++) aw[j] = expf(w_o[b0 + j] - mx) / ssum;

        // inline bucket prefix: h_start = fold over previous chunks' D
        float cL[4];
        #pragma unroll
        for (int j = 0; j < 4; j++) cL[j] = powf(c1[j], (float)LF);
        float hh[4] = {0, 0, 0, 0};
        for (int k = 0; k < chunk; k++) {
            const float4 D = ((const float4*)g_D)[k * L4 + lane4];
            hh[0] = cL[0] * hh[0] + D.x;
            hh[1] = cL[1] * hh[1] + D.y;
            hh[2] = cL[2] * hh[2] + D.z;
            hh[3] = cL[3] * hh[3] + D.w;
        }

        const float4 s0 = ((const float4*)g_sstart)[chunk * L4 + lane4];
        float s[4] = {s0.x, s0.y, s0.z, s0.w};
        float4* H4 = (float4*)H + (size_t)t0 * L4 + lane4;

        float pa[4], ta[4];
        #pragma unroll
        for (int j = 0; j < 4; j++) {
            pa[j] = __ldg(Pp + (t0 + j) * NS);
            ta[j] = __ldg(Tp + (t0 + j) * NS);
        }
        for (int g0 = 0; g0 < nG; g0++) {
            float pb[4], tb[4];
            const int kn = (g0 + 1 < nG) ? (g0 + 1) * 4 : (len - 4);
            #pragma unroll
            for (int j = 0; j < 4; j++) {
                pb[j] = __ldg(Pp + (t0 + kn + j) * NS);
                tb[j] = __ldg(Tp + (t0 + kn + j) * NS);
            }
            #pragma unroll
            for (int u = 0; u < 4; u++) {
                const int k = g0 * 4 + u;
                const float tpos = fmaxf(ta[u], 0.0f);
                const float pneg = (ta[u] < 0.0f) ? pa[u] : 0.0f;
                const float ppos = (ta[u] > 0.0f) ? pa[u] : 0.0f;
                float hn[4];
                float qa = 0.0f;
                #pragma unroll
                for (int j = 0; j < 4; j++) {
                    const float sm  = tpos * melt[j];
                    const float m   = fminf(sm, s[j]);
                    s[j] = s[j] - m + pneg;
                    const float xin = (ppos + m) * gi[j];
                    const float u2  = xin + hh[j];
                    const float q   = u2 * gl[j];
                    hn[j] = u2 - q;
                    hh[j] = hn[j];
                    qa = fmaf(q, aw[j], qa);
                }
                __stcs(&H4[(size_t)k * L4], make_float4(hn[0], hn[1], hn[2], hn[3]));

                qa += __shfl_xor_sync(0xFFFFFFFFu, qa, 1);
                qa += __shfl_xor_sync(0xFFFFFFFFu, qa, 2);
                if (bg == 0) __stcs(&Q[(t0 + k) * NS + site], qa);
            }
            #pragma unroll
            for (int j = 0; j < 4; j++) { pa[j] = pb[j]; ta[j] = tb[j]; }
        }
    }
}

extern "C" void kernel_launch(void* const* d_in, const int* in_sizes, int n_in,
                              void* d_out, int out_size)
{
    const float* P   = (const float*)d_in[0];
    const float* T   = (const float*)d_in[1];
    const float* w_i = (const float*)d_in[2];
    const float* w_o = (const float*)d_in[3];
    const float* w_l = (const float*)d_in[4];
    const float* w_s = (const float*)d_in[5];

    float* Q = (float*)d_out;
    float* H = Q + (size_t)NT * NS;
    float* S = H + (size_t)NT * NS * NH;

    waternet_fused<<<NBLOCKS, BLK>>>(P, T, w_i, w_o, w_l, w_s, Q, H, S);
}

// round 8
// speedup vs baseline: 2.7280x; 1.0236x over previous
#include <cuda_runtime.h>
#include <math.h>

// WaterNetModel: chunk-parallel scan, fused persistent kernel.
// Round 8: snow slope-sum linearity (A = Psum - melt*Tsum), algebraic trims
// (hn = c1*u2, qa += glaw*u2, D via fused cg), chunk rebalance 14x68 + 2x72.
// Snow: s' = max(s + a, b) (max-plus, composable).
// Bucket: h' = c1*(h + xin), constant c1 (affine, composable).
// Outputs: Q [NT,NS] | H [NT,NS,NH] | S [NT,NS,NH].

#define NT 1096
#define NS 2048
#define NH 16
#define C16 16
#define CA 32
#define LANES (NS * NH)        // 32768
#define L4    (LANES / 4)      // 8192
#define NTHREADS (C16 * L4)    // 131072
#define BLK 128
#define NBLOCKS (NTHREADS / BLK)  // 1024 (8 CTAs/SM -> all resident)

// scratch
__device__ float g_Ps[CA * NS];          // 256 KB  per-chunk sum of pneg
__device__ float g_Ts[CA * NS];          // 256 KB  per-chunk sum of tpos
__device__ float g_B[CA * LANES];        // 4 MB    snow compose floor
__device__ float g_sstart[C16 * LANES];  // 2 MB    C-chunk start snow state
__device__ float g_D[C16 * LANES];       // 2 MB    bucket chunk offsets

__device__ unsigned g_bar = 0;
__device__ unsigned g_gen = 0;

__device__ __forceinline__ void grid_sync()
{
    __syncthreads();
    if (threadIdx.x == 0) {
        __threadfence();
        unsigned gen = *(volatile unsigned*)&g_gen;
        unsigned arr = atomicAdd(&g_bar, 1u);
        if (arr == (unsigned)gridDim.x - 1u) {
            g_bar = 0;
            __threadfence();
            *(volatile unsigned*)&g_gen = gen + 1u;
        } else {
            while (*(volatile unsigned*)&g_gen == gen) { __nanosleep(32); }
        }
        __threadfence();
    }
    __syncthreads();
}

// chunk geometry: chunks 0..13 len 68, chunks 14..15 len 72
__device__ __forceinline__ int c_t0(int c)  { return (c < 14) ? 68 * c : 952 + 72 * (c - 14); }
__device__ __forceinline__ int c_len(int c) { return (c < 14) ? 68 : 72; }

__global__ __launch_bounds__(BLK, 8)
void waternet_fused(const float* __restrict__ P, const float* __restrict__ T,
                    const float* __restrict__ w_i, const float* __restrict__ w_o,
                    const float* __restrict__ w_l, const float* __restrict__ w_s,
                    float* __restrict__ Q, float* __restrict__ H,
                    float* __restrict__ S)
{
    const int g = blockIdx.x * BLK + threadIdx.x;   // [0, NTHREADS)

    // =============== Phase A: snow composition (half-site, 8 buckets) ====
    {
        const int caA   = g >> 12;          // A-chunk [0,32)
        const int rem   = g & 4095;
        const int siteA = rem >> 1;
        const int half  = rem & 1;
        const int b0A   = half * 8;

        const int c16A = caA >> 1;
        const int lenA = (caA >= 28) ? 36 : ((caA & 1) ? 32 : 36);
        const int t0A  = c_t0(c16A) + ((caA & 1) ? 36 : 0);
        const int nGA  = lenA >> 2;

        float nm[8];                        // -melt
        #pragma unroll
        for (int j = 0; j < 8; j++) nm[j] = -(expf(w_s[b0A + j]) + 1.0f);

        float B[8];
        #pragma unroll
        for (int j = 0; j < 8; j++) B[j] = -INFINITY;
        float Ps = 0.0f, Ts = 0.0f;

        const float* PpA = P + siteA;
        const float* TpA = T + siteA;

        float pa[4], ta[4];
        #pragma unroll
        for (int j = 0; j < 4; j++) {
            pa[j] = __ldg(PpA + (t0A + j) * NS);
            ta[j] = __ldg(TpA + (t0A + j) * NS);
        }
        for (int g0 = 0; g0 < nGA; g0++) {
            float pb[4], tb[4];
            const int kn = (g0 + 1 < nGA) ? (g0 + 1) * 4 : (lenA - 4);
            #pragma unroll
            for (int j = 0; j < 4; j++) {
                pb[j] = __ldg(PpA + (t0A + kn + j) * NS);
                tb[j] = __ldg(TpA + (t0A + kn + j) * NS);
            }
            #pragma unroll
            for (int u = 0; u < 4; u++) {
                const float tpos = fmaxf(ta[u], 0.0f);
                const float pneg = (ta[u] < 0.0f) ? pa[u] : 0.0f;
                Ps += pneg;
                Ts += tpos;
                #pragma unroll
                for (int j = 0; j < 8; j++) {
                    const float a = fmaf(tpos, nm[j], pneg);
                    B[j] = fmaxf(B[j] + a, pneg);
                }
            }
            #pragma unroll
            for (int j = 0; j < 4; j++) { pa[j] = pb[j]; ta[j] = tb[j]; }
        }

        float4* dB = (float4*)&g_B[caA * LANES + siteA * NH + b0A];
        dB[0] = make_float4(B[0], B[1], B[2], B[3]);
        dB[1] = make_float4(B[4], B[5], B[6], B[7]);
        if (half == 0) {
            g_Ps[caA * NS + siteA] = Ps;
            g_Ts[caA * NS + siteA] = Ts;
        }
    }
    grid_sync();

    // =============== Phase B: chunk-start snow states (lane threads) =====
    if (g < LANES) {
        const int hB    = g & 15;
        const int siteB = g >> 4;
        const float meltB = expf(w_s[hB]) + 1.0f;
        float s = 0.0f;
        #pragma unroll
        for (int ca = 0; ca < CA; ca++) {
            if ((ca & 1) == 0) g_sstart[(ca >> 1) * LANES + g] = s;
            const float A = g_Ps[ca * NS + siteB] - meltB * g_Ts[ca * NS + siteB];
            s = fmaxf(s + A, g_B[ca * LANES + g]);
        }
    }
    grid_sync();

    // ---- common decode for phases C and E (quad threads) ----
    const int lane4 = g & (L4 - 1);
    const int chunk = g >> 13;
    const int site  = lane4 >> 2;
    const int bg    = lane4 & 3;
    const int b0    = bg * 4;

    const int t0  = c_t0(chunk);
    const int len = c_len(chunk);
    const int nG  = len >> 2;

    const float* Pp = P + site;
    const float* Tp = T + site;

    // =============== Phase C: replay snow, write S, accumulate D =========
    {
        float melt[4], c1[4], cg[4];
        #pragma unroll
        for (int j = 0; j < 4; j++) {
            melt[j] = expf(w_s[b0 + j]) + 1.0f;
            const float gi = 1.0f / (1.0f + expf(-w_i[b0 + j]));
            c1[j] = 1.0f - 1.0f / (1.0f + expf(-w_l[b0 + j]));
            cg[j] = c1[j] * gi;
        }

        const float4 s0 = ((const float4*)g_sstart)[chunk * L4 + lane4];
        float s[4] = {s0.x, s0.y, s0.z, s0.w};
        float D[4] = {0, 0, 0, 0};
        float4* S4 = (float4*)S + (size_t)t0 * L4 + lane4;

        float pa[4], ta[4];
        #pragma unroll
        for (int j = 0; j < 4; j++) {
            pa[j] = __ldg(Pp + (t0 + j) * NS);
            ta[j] = __ldg(Tp + (t0 + j) * NS);
        }
        for (int g0 = 0; g0 < nG; g0++) {
            float pb[4], tb[4];
            const int kn = (g0 + 1 < nG) ? (g0 + 1) * 4 : (len - 4);
            #pragma unroll
            for (int j = 0; j < 4; j++) {
                pb[j] = __ldg(Pp + (t0 + kn + j) * NS);
                tb[j] = __ldg(Tp + (t0 + kn + j) * NS);
            }
            #pragma unroll
            for (int u = 0; u < 4; u++) {
                const int k = g0 * 4 + u;
                const float tpos = fmaxf(ta[u], 0.0f);
                const float pneg = (ta[u] < 0.0f) ? pa[u] : 0.0f;
                const float ppos = (ta[u] > 0.0f) ? pa[u] : 0.0f;
                float sn[4];
                #pragma unroll
                for (int j = 0; j < 4; j++) {
                    const float sm = tpos * melt[j];
                    const float m  = fminf(sm, s[j]);
                    sn[j] = (s[j] - m) + pneg;
                    const float t1 = ppos + m;
                    D[j] = fmaf(c1[j], D[j], cg[j] * t1);
                    s[j] = sn[j];
                }
                __stcs(&S4[(size_t)k * L4], make_float4(sn[0], sn[1], sn[2], sn[3]));
            }
            #pragma unroll
            for (int j = 0; j < 4; j++) { pa[j] = pb[j]; ta[j] = tb[j]; }
        }
        ((float4*)g_D)[chunk * L4 + lane4] = make_float4(D[0], D[1], D[2], D[3]);
    }
    grid_sync();

    // =============== Phase E: inline h_start, replay, write H and Q ======
    {
        float melt[4], gi[4], c1[4], glaw[4];
        {
            float mx = w_o[0];
            #pragma unroll
            for (int j = 1; j < NH; j++) mx = fmaxf(mx, w_o[j]);
            float ssum = 0.0f;
            #pragma unroll
            for (int j = 0; j < NH; j++) ssum += expf(w_o[j] - mx);
            #pragma unroll
            for (int j = 0; j < 4; j++) {
                melt[j] = expf(w_s[b0 + j]) + 1.0f;
                gi[j]   = 1.0f / (1.0f + expf(-w_i[b0 + j]));
                const float gl = 1.0f / (1.0f + expf(-w_l[b0 + j]));
                c1[j]   = 1.0f - gl;
                glaw[j] = gl * (expf(w_o[b0 + j] - mx) / ssum);
            }
        }

        // h_start: fold over previous chunks' D (len-dependent decay)
        float hh[4] = {0, 0, 0, 0};
        {
            float c68[4], c72[4];
            #pragma unroll
            for (int j = 0; j < 4; j++) {
                const float x2  = c1[j] * c1[j];
                const float x4  = x2 * x2;
                const float x8  = x4 * x4;
                const float x16 = x8 * x8;
                const float x32 = x16 * x16;
                const float x64 = x32 * x32;
                c68[j] = x64 * x4;
                c72[j] = c68[j] * x4;
            }
            for (int k = 0; k < chunk; k++) {
                const float4 D = ((const float4*)g_D)[k * L4 + lane4];
                const bool big = (k >= 14);
                hh[0] = (big ? c72[0] : c68[0]) * hh[0] + D.x;
                hh[1] = (big ? c72[1] : c68[1]) * hh[1] + D.y;
                hh[2] = (big ? c72[2] : c68[2]) * hh[2] + D.z;
                hh[3] = (big ? c72[3] : c68[3]) * hh[3] + D.w;
            }
        }

        const float4 s0 = ((const float4*)g_sstart)[chunk * L4 + lane4];
        float s[4] = {s0.x, s0.y, s0.z, s0.w};
        float4* H4 = (float4*)H + (size_t)t0 * L4 + lane4;

        float pa[4], ta[4];
        #pragma unroll
        for (int j = 0; j < 4; j++) {
            pa[j] = __ldg(Pp + (t0 + j) * NS);
            ta[j] = __ldg(Tp + (t0 + j) * NS);
        }
        for (int g0 = 0; g0 < nG; g0++) {
            float pb[4], tb[4];
            const int kn = (g0 + 1 < nG) ? (g0 + 1) * 4 : (len - 4);
            #pragma unroll
            for (int j = 0; j < 4; j++) {
                pb[j] = __ldg(Pp + (t0 + kn + j) * NS);
                tb[j] = __ldg(Tp + (t0 + kn + j) * NS);
            }
            #pragma unroll
            for (int u = 0; u < 4; u++) {
                const int k = g0 * 4 + u;
                const float tpos = fmaxf(ta[u], 0.0f);
                const float pneg = (ta[u] < 0.0f) ? pa[u] : 0.0f;
                const float ppos = (ta[u] > 0.0f) ? pa[u] : 0.0f;
                float hn[4];
                float qa = 0.0f;
                #pragma unroll
                for (int j = 0; j < 4; j++) {
                    const float sm  = tpos * melt[j];
                    const float m   = fminf(sm, s[j]);
                    s[j] = (s[j] - m) + pneg;
                    const float xin = (ppos + m) * gi[j];
                    const float u2  = xin + hh[j];
                    hn[j] = c1[j] * u2;            // h - q + xin
                    hh[j] = hn[j];
                    qa = fmaf(u2, glaw[j], qa);    // q*a = u2*gl*a
                }
                __stcs(&H4[(size_t)k * L4], make_float4(hn[0], hn[1], hn[2], hn[3]));

                qa += __shfl_xor_sync(0xFFFFFFFFu, qa, 1);
                qa += __shfl_xor_sync(0xFFFFFFFFu, qa, 2);
                if (bg == 0) __stcs(&Q[(t0 + k) * NS + site], qa);
            }
            #pragma unroll
            for (int j = 0; j < 4; j++) { pa[j] = pb[j]; ta[j] = tb[j]; }
        }
    }
}

extern "C" void kernel_launch(void* const* d_in, const int* in_sizes, int n_in,
                              void* d_out, int out_size)
{
    const float* P   = (const float*)d_in[0];
    const float* T   = (const float*)d_in[1];
    const float* w_i = (const float*)d_in[2];
    const float* w_o = (const float*)d_in[3];
    const float* w_l = (const float*)d_in[4];
    const float* w_s = (const float*)d_in[5];

    float* Q = (float*)d_out;
    float* H = Q + (size_t)NT * NS;
    float* S = H + (size_t)NT * NS * NH;

    waternet_fused<<<NBLOCKS, BLK>>>(P, T, w_i, w_o, w_l, w_s, Q, H, S);
}

// round 9
// speedup vs baseline: 2.9133x; 1.0679x over previous
#include <cuda_runtime.h>
#include <math.h>

// WaterNetModel: chunk-parallel scan, fused persistent kernel.
// Round 9: phase B (serial snow prefix) removed — each phase-C thread folds
// its own s_start from the A-summaries in its prolog (distributed, no barrier,
// chunk 0 starts storing immediately). 2 grid_syncs total.
// Snow: s' = max(s + a, b) (max-plus, composable); A = Psum - melt*Tsum.
// Bucket: h' = c1*(h + xin), constant c1 (affine, composable).
// Outputs: Q [NT,NS] | H [NT,NS,NH] | S [NT,NS,NH].

#define NT 1096
#define NS 2048
#define NH 16
#define C16 16
#define CA 32
#define LANES (NS * NH)        // 32768
#define L4    (LANES / 4)      // 8192
#define NTHREADS (C16 * L4)    // 131072
#define BLK 128
#define NBLOCKS (NTHREADS / BLK)  // 1024 (8 CTAs/SM -> all resident)

// scratch
__device__ float g_Ps[CA * NS];          // per-A-chunk sum of pneg
__device__ float g_Ts[CA * NS];          // per-A-chunk sum of tpos
__device__ float g_B[CA * LANES];        // snow compose floor
__device__ float g_sstart[C16 * LANES];  // C-chunk start snow state (C -> E)
__device__ float g_D[C16 * LANES];       // bucket chunk offsets

__device__ unsigned g_bar = 0;
__device__ unsigned g_gen = 0;

__device__ __forceinline__ void grid_sync()
{
    __syncthreads();
    if (threadIdx.x == 0) {
        __threadfence();
        unsigned gen = *(volatile unsigned*)&g_gen;
        unsigned arr = atomicAdd(&g_bar, 1u);
        if (arr == (unsigned)gridDim.x - 1u) {
            g_bar = 0;
            __threadfence();
            *(volatile unsigned*)&g_gen = gen + 1u;
        } else {
            while (*(volatile unsigned*)&g_gen == gen) { __nanosleep(32); }
        }
        __threadfence();
    }
    __syncthreads();
}

// C-chunk geometry: chunks 0..13 len 68, chunks 14..15 len 72
__device__ __forceinline__ int c_t0(int c)  { return (c < 14) ? 68 * c : 952 + 72 * (c - 14); }
__device__ __forceinline__ int c_len(int c) { return (c < 14) ? 68 : 72; }

__global__ __launch_bounds__(BLK, 8)
void waternet_fused(const float* __restrict__ P, const float* __restrict__ T,
                    const float* __restrict__ w_i, const float* __restrict__ w_o,
                    const float* __restrict__ w_l, const float* __restrict__ w_s,
                    float* __restrict__ Q, float* __restrict__ H,
                    float* __restrict__ S)
{
    const int g = blockIdx.x * BLK + threadIdx.x;   // [0, NTHREADS)

    // =============== Phase A: snow composition (half-site, 8 buckets) ====
    {
        const int caA   = g >> 12;          // A-chunk [0,32)
        const int rem   = g & 4095;
        const int siteA = rem >> 1;
        const int half  = rem & 1;
        const int b0A   = half * 8;

        const int c16A = caA >> 1;
        const int lenA = (caA >= 28) ? 36 : ((caA & 1) ? 32 : 36);
        const int t0A  = c_t0(c16A) + ((caA & 1) ? 36 : 0);
        const int nGA  = lenA >> 2;

        float nm[8];                        // -melt
        #pragma unroll
        for (int j = 0; j < 8; j++) nm[j] = -(expf(w_s[b0A + j]) + 1.0f);

        float B[8];
        #pragma unroll
        for (int j = 0; j < 8; j++) B[j] = -INFINITY;
        float Ps = 0.0f, Ts = 0.0f;

        const float* PpA = P + siteA;
        const float* TpA = T + siteA;

        float pa[4], ta[4];
        #pragma unroll
        for (int j = 0; j < 4; j++) {
            pa[j] = __ldg(PpA + (t0A + j) * NS);
            ta[j] = __ldg(TpA + (t0A + j) * NS);
        }
        for (int g0 = 0; g0 < nGA; g0++) {
            float pb[4], tb[4];
            const int kn = (g0 + 1 < nGA) ? (g0 + 1) * 4 : (lenA - 4);
            #pragma unroll
            for (int j = 0; j < 4; j++) {
                pb[j] = __ldg(PpA + (t0A + kn + j) * NS);
                tb[j] = __ldg(TpA + (t0A + kn + j) * NS);
            }
            #pragma unroll
            for (int u = 0; u < 4; u++) {
                const float tpos = fmaxf(ta[u], 0.0f);
                const float pneg = (ta[u] < 0.0f) ? pa[u] : 0.0f;
                Ps += pneg;
                Ts += tpos;
                #pragma unroll
                for (int j = 0; j < 8; j++) {
                    const float a = fmaf(tpos, nm[j], pneg);
                    B[j] = fmaxf(B[j] + a, pneg);
                }
            }
            #pragma unroll
            for (int j = 0; j < 4; j++) { pa[j] = pb[j]; ta[j] = tb[j]; }
        }

        float4* dB = (float4*)&g_B[caA * LANES + siteA * NH + b0A];
        dB[0] = make_float4(B[0], B[1], B[2], B[3]);
        dB[1] = make_float4(B[4], B[5], B[6], B[7]);
        if (half == 0) {
            g_Ps[caA * NS + siteA] = Ps;
            g_Ts[caA * NS + siteA] = Ts;
        }
    }
    grid_sync();

    // ---- common decode for phases C and E (quad threads) ----
    const int lane4 = g & (L4 - 1);
    const int chunk = g >> 13;
    const int site  = lane4 >> 2;
    const int bg    = lane4 & 3;
    const int b0    = bg * 4;

    const int t0  = c_t0(chunk);
    const int len = c_len(chunk);
    const int nG  = len >> 2;

    const float* Pp = P + site;
    const float* Tp = T + site;

    // =============== Phase C: inline s_start fold, replay snow, write S ==
    {
        float melt[4], c1[4], cg[4];
        #pragma unroll
        for (int j = 0; j < 4; j++) {
            melt[j] = expf(w_s[b0 + j]) + 1.0f;
            const float gi = 1.0f / (1.0f + expf(-w_i[b0 + j]));
            c1[j] = 1.0f - 1.0f / (1.0f + expf(-w_l[b0 + j]));
            cg[j] = c1[j] * gi;
        }

        // distributed s_start fold over preceding A-chunks (loads independent)
        float s[4] = {0, 0, 0, 0};
        {
            const int nca = chunk * 2;
            #pragma unroll 2
            for (int ca = 0; ca < nca; ca++) {
                const float Ps = g_Ps[ca * NS + site];
                const float Ts = g_Ts[ca * NS + site];
                const float4 B = ((const float4*)g_B)[ca * L4 + lane4];
                s[0] = fmaxf(s[0] + fmaf(-melt[0], Ts, Ps), B.x);
                s[1] = fmaxf(s[1] + fmaf(-melt[1], Ts, Ps), B.y);
                s[2] = fmaxf(s[2] + fmaf(-melt[2], Ts, Ps), B.z);
                s[3] = fmaxf(s[3] + fmaf(-melt[3], Ts, Ps), B.w);
            }
        }
        // publish for phase E
        ((float4*)g_sstart)[chunk * L4 + lane4] = make_float4(s[0], s[1], s[2], s[3]);

        float D[4] = {0, 0, 0, 0};
        float4* S4 = (float4*)S + (size_t)t0 * L4 + lane4;

        float pa[4], ta[4];
        #pragma unroll
        for (int j = 0; j < 4; j++) {
            pa[j] = __ldg(Pp + (t0 + j) * NS);
            ta[j] = __ldg(Tp + (t0 + j) * NS);
        }
        for (int g0 = 0; g0 < nG; g0++) {
            float pb[4], tb[4];
            const int kn = (g0 + 1 < nG) ? (g0 + 1) * 4 : (len - 4);
            #pragma unroll
            for (int j = 0; j < 4; j++) {
                pb[j] = __ldg(Pp + (t0 + kn + j) * NS);
                tb[j] = __ldg(Tp + (t0 + kn + j) * NS);
            }
            #pragma unroll
            for (int u = 0; u < 4; u++) {
                const int k = g0 * 4 + u;
                const float tpos = fmaxf(ta[u], 0.0f);
                const float pneg = (ta[u] < 0.0f) ? pa[u] : 0.0f;
                const float ppos = (ta[u] > 0.0f) ? pa[u] : 0.0f;
                float sn[4];
                #pragma unroll
                for (int j = 0; j < 4; j++) {
                    const float sm = tpos * melt[j];
                    const float m  = fminf(sm, s[j]);
                    sn[j] = (s[j] - m) + pneg;
                    const float t1 = ppos + m;
                    D[j] = fmaf(c1[j], D[j], cg[j] * t1);
                    s[j] = sn[j];
                }
                __stcs(&S4[(size_t)k * L4], make_float4(sn[0], sn[1], sn[2], sn[3]));
            }
            #pragma unroll
            for (int j = 0; j < 4; j++) { pa[j] = pb[j]; ta[j] = tb[j]; }
        }
        ((float4*)g_D)[chunk * L4 + lane4] = make_float4(D[0], D[1], D[2], D[3]);
    }
    grid_sync();

    // =============== Phase E: inline h_start, replay, write H and Q ======
    {
        float melt[4], gi[4], c1[4], glaw[4];
        {
            float mx = w_o[0];
            #pragma unroll
            for (int j = 1; j < NH; j++) mx = fmaxf(mx, w_o[j]);
            float ssum = 0.0f;
            #pragma unroll
            for (int j = 0; j < NH; j++) ssum += expf(w_o[j] - mx);
            #pragma unroll
            for (int j = 0; j < 4; j++) {
                melt[j] = expf(w_s[b0 + j]) + 1.0f;
                gi[j]   = 1.0f / (1.0f + expf(-w_i[b0 + j]));
                const float gl = 1.0f / (1.0f + expf(-w_l[b0 + j]));
                c1[j]   = 1.0f - gl;
                glaw[j] = gl * (expf(w_o[b0 + j] - mx) / ssum);
            }
        }

        // h_start: fold over previous chunks' D (len-dependent decay)
        float hh[4] = {0, 0, 0, 0};
        {
            float c68[4], c72[4];
            #pragma unroll
            for (int j = 0; j < 4; j++) {
                const float x2  = c1[j] * c1[j];
                const float x4  = x2 * x2;
                const float x8  = x4 * x4;
                const float x16 = x8 * x8;
                const float x32 = x16 * x16;
                const float x64 = x32 * x32;
                c68[j] = x64 * x4;
                c72[j] = c68[j] * x4;
            }
            #pragma unroll 2
            for (int k = 0; k < chunk; k++) {
                const float4 D = ((const float4*)g_D)[k * L4 + lane4];
                const bool big = (k >= 14);
                hh[0] = (big ? c72[0] : c68[0]) * hh[0] + D.x;
                hh[1] = (big ? c72[1] : c68[1]) * hh[1] + D.y;
                hh[2] = (big ? c72[2] : c68[2]) * hh[2] + D.z;
                hh[3] = (big ? c72[3] : c68[3]) * hh[3] + D.w;
            }
        }

        const float4 s0 = ((const float4*)g_sstart)[chunk * L4 + lane4];
        float s[4] = {s0.x, s0.y, s0.z, s0.w};
        float4* H4 = (float4*)H + (size_t)t0 * L4 + lane4;

        float pa[4], ta[4];
        #pragma unroll
        for (int j = 0; j < 4; j++) {
            pa[j] = __ldg(Pp + (t0 + j) * NS);
            ta[j] = __ldg(Tp + (t0 + j) * NS);
        }
        for (int g0 = 0; g0 < nG; g0++) {
            float pb[4], tb[4];
            const int kn = (g0 + 1 < nG) ? (g0 + 1) * 4 : (len - 4);
            #pragma unroll
            for (int j = 0; j < 4; j++) {
                pb[j] = __ldg(Pp + (t0 + kn + j) * NS);
                tb[j] = __ldg(Tp + (t0 + kn + j) * NS);
            }
            #pragma unroll
            for (int u = 0; u < 4; u++) {
                const int k = g0 * 4 + u;
                const float tpos = fmaxf(ta[u], 0.0f);
                const float pneg = (ta[u] < 0.0f) ? pa[u] : 0.0f;
                const float ppos = (ta[u] > 0.0f) ? pa[u] : 0.0f;
                float hn[4];
                float qa = 0.0f;
                #pragma unroll
                for (int j = 0; j < 4; j++) {
                    const float sm  = tpos * melt[j];
                    const float m   = fminf(sm, s[j]);
                    s[j] = (s[j] - m) + pneg;
                    const float xin = (ppos + m) * gi[j];
                    const float u2  = xin + hh[j];
                    hn[j] = c1[j] * u2;            // h - q + xin
                    hh[j] = hn[j];
                    qa = fmaf(u2, glaw[j], qa);    // q*a = u2*gl*a
                }
                __stcs(&H4[(size_t)k * L4], make_float4(hn[0], hn[1], hn[2], hn[3]));

                qa += __shfl_xor_sync(0xFFFFFFFFu, qa, 1);
                qa += __shfl_xor_sync(0xFFFFFFFFu, qa, 2);
                if (bg == 0) __stcs(&Q[(t0 + k) * NS + site], qa);
            }
            #pragma unroll
            for (int j = 0; j < 4; j++) { pa[j] = pb[j]; ta[j] = tb[j]; }
        }
    }
}

extern "C" void kernel_launch(void* const* d_in, const int* in_sizes, int n_in,
                              void* d_out, int out_size)
{
    const float* P   = (const float*)d_in[0];
    const float* T   = (const float*)d_in[1];
    const float* w_i = (const float*)d_in[2];
    const float* w_o = (const float*)d_in[3];
    const float* w_l = (const float*)d_in[4];
    const float* w_s = (const float*)d_in[5];

    float* Q = (float*)d_out;
    float* H = Q + (size_t)NT * NS;
    float* S = H + (size_t)NT * NS * NH;

    waternet_fused<<<NBLOCKS, BLK>>>(P, T, w_i, w_o, w_l, w_s, Q, H, S);
}

// round 10
// speedup vs baseline: 3.0756x; 1.0557x over previous
#include <cuda_runtime.h>
#include <math.h>

// WaterNetModel: chunk-parallel scan, fused persistent kernel.
// Round 10: P/T staged in shared memory once per block (phase C's slab is
// reused by phase E — zero global input loads in E). Phase A stages its own
// slab (no duplicate loads). launch_bounds(128,9) for 56% occupancy cap.
// Snow: s' = max(s + a, b) (max-plus, composable); A = Psum - melt*Tsum.
// Bucket: h' = c1*(h + xin), constant c1 (affine, composable).
// Outputs: Q [NT,NS] | H [NT,NS,NH] | S [NT,NS,NH].

#define NT 1096
#define NS 2048
#define NH 16
#define C16 16
#define CA 32
#define LANES (NS * NH)        // 32768
#define L4    (LANES / 4)      // 8192
#define NTHREADS (C16 * L4)    // 131072
#define BLK 128
#define NBLOCKS (NTHREADS / BLK)  // 1024 (9 CTAs/SM -> all resident)

// scratch
__device__ float g_Ps[CA * NS];          // per-A-chunk sum of pneg
__device__ float g_Ts[CA * NS];          // per-A-chunk sum of tpos
__device__ float g_B[CA * LANES];        // snow compose floor
__device__ float g_sstart[C16 * LANES];  // C-chunk start snow state (C -> E)
__device__ float g_D[C16 * LANES];       // bucket chunk offsets

__device__ unsigned g_bar = 0;
__device__ unsigned g_gen = 0;

__device__ __forceinline__ void grid_sync()
{
    __syncthreads();
    if (threadIdx.x == 0) {
        __threadfence();
        unsigned gen = *(volatile unsigned*)&g_gen;
        unsigned arr = atomicAdd(&g_bar, 1u);
        if (arr == (unsigned)gridDim.x - 1u) {
            g_bar = 0;
            __threadfence();
            *(volatile unsigned*)&g_gen = gen + 1u;
        } else {
            while (*(volatile unsigned*)&g_gen == gen) { __nanosleep(32); }
        }
        __threadfence();
    }
    __syncthreads();
}

// C-chunk geometry: chunks 0..13 len 68, chunks 14..15 len 72
__device__ __forceinline__ int c_t0(int c)  { return (c < 14) ? 68 * c : 952 + 72 * (c - 14); }
__device__ __forceinline__ int c_len(int c) { return (c < 14) ? 68 : 72; }

__global__ __launch_bounds__(BLK, 9)
void waternet_fused(const float* __restrict__ P, const float* __restrict__ T,
                    const float* __restrict__ w_i, const float* __restrict__ w_o,
                    const float* __restrict__ w_l, const float* __restrict__ w_s,
                    float* __restrict__ Q, float* __restrict__ H,
                    float* __restrict__ S)
{
    // smem slabs: phase A uses [lenA<=40][64 sites]; phases C/E use [len<=72][32 sites]
    __shared__ float smP[2560];
    __shared__ float smT[2560];

    const int tid = threadIdx.x;
    const int g   = blockIdx.x * BLK + tid;   // [0, NTHREADS)

    // =============== Phase A: snow composition (half-site, 8 buckets) ====
    {
        const int caA  = g >> 12;              // A-chunk [0,32), uniform per block
        const int s0A  = ((blockIdx.x * BLK) & 4095) >> 1;
        const int slA  = tid >> 1;             // local site [0,64)
        const int half = tid & 1;
        const int b0A  = half * 8;

        const int c16A = caA >> 1;
        const int lenA = (caA >= 28) ? 36 : ((caA & 1) ? 32 : 36);
        const int t0A  = c_t0(c16A) + ((caA & 1) ? 36 : 0);

        // stage slab: one LDG per element per block, coalesced 128B
        for (int e = tid; e < lenA * 64; e += BLK) {
            const int t = e >> 6, j = e & 63;
            smP[e] = __ldg(P + (t0A + t) * NS + s0A + j);
            smT[e] = __ldg(T + (t0A + t) * NS + s0A + j);
        }

        float nm[8];                           // -melt
        #pragma unroll
        for (int j = 0; j < 8; j++) nm[j] = -(expf(w_s[b0A + j]) + 1.0f);

        __syncthreads();

        float B[8];
        #pragma unroll
        for (int j = 0; j < 8; j++) B[j] = -INFINITY;
        float Ps = 0.0f, Ts = 0.0f;

        #pragma unroll 4
        for (int k = 0; k < lenA; k++) {
            const float Tk = smT[k * 64 + slA];
            const float Pk = smP[k * 64 + slA];
            const float tpos = fmaxf(Tk, 0.0f);
            const float pneg = (Tk < 0.0f) ? Pk : 0.0f;
            Ps += pneg;
            Ts += tpos;
            #pragma unroll
            for (int j = 0; j < 8; j++) {
                const float a = fmaf(tpos, nm[j], pneg);
                B[j] = fmaxf(B[j] + a, pneg);
            }
        }

        const int siteA = s0A + slA;
        float4* dB = (float4*)&g_B[caA * LANES + siteA * NH + b0A];
        dB[0] = make_float4(B[0], B[1], B[2], B[3]);
        dB[1] = make_float4(B[4], B[5], B[6], B[7]);
        if (half == 0) {
            g_Ps[caA * NS + siteA] = Ps;
            g_Ts[caA * NS + siteA] = Ts;
        }
    }
    grid_sync();

    // ---- common decode for phases C and E (quad threads) ----
    const int lane4 = g & (L4 - 1);
    const int chunk = g >> 13;
    const int site  = lane4 >> 2;
    const int bg    = tid & 3;                 // == lane4 & 3
    const int b0    = bg * 4;
    const int sl    = tid >> 2;                // local site [0,32)

    const int t0  = c_t0(chunk);
    const int len = c_len(chunk);
    const int nG  = len >> 2;

    // =============== Phase C: stage slab, fold s_start, replay, write S ==
    {
        // stage this chunk's 32-site slab (reused by phase E!)
        const int s0 = ((blockIdx.x * BLK) & (L4 - 1)) >> 2;
        for (int e = tid; e < len * 32; e += BLK) {
            const int t = e >> 5, j = e & 31;
            smP[e] = __ldg(P + (t0 + t) * NS + s0 + j);
            smT[e] = __ldg(T + (t0 + t) * NS + s0 + j);
        }

        float melt[4], c1[4], cg[4];
        #pragma unroll
        for (int j = 0; j < 4; j++) {
            melt[j] = expf(w_s[b0 + j]) + 1.0f;
            const float gi = 1.0f / (1.0f + expf(-w_i[b0 + j]));
            c1[j] = 1.0f - 1.0f / (1.0f + expf(-w_l[b0 + j]));
            cg[j] = c1[j] * gi;
        }

        // distributed s_start fold (overlaps staging LDG flight)
        float s[4] = {0, 0, 0, 0};
        {
            const int nca = chunk * 2;
            #pragma unroll 2
            for (int ca = 0; ca < nca; ca++) {
                const float Ps = g_Ps[ca * NS + site];
                const float Ts = g_Ts[ca * NS + site];
                const float4 B = ((const float4*)g_B)[ca * L4 + lane4];
                s[0] = fmaxf(s[0] + fmaf(-melt[0], Ts, Ps), B.x);
                s[1] = fmaxf(s[1] + fmaf(-melt[1], Ts, Ps), B.y);
                s[2] = fmaxf(s[2] + fmaf(-melt[2], Ts, Ps), B.z);
                s[3] = fmaxf(s[3] + fmaf(-melt[3], Ts, Ps), B.w);
            }
        }
        ((float4*)g_sstart)[chunk * L4 + lane4] = make_float4(s[0], s[1], s[2], s[3]);

        __syncthreads();

        float D[4] = {0, 0, 0, 0};
        float4* S4 = (float4*)S + (size_t)t0 * L4 + lane4;

        for (int g0 = 0; g0 < nG; g0++) {
            #pragma unroll
            for (int u = 0; u < 4; u++) {
                const int k = g0 * 4 + u;
                const float Tk = smT[k * 32 + sl];
                const float Pk = smP[k * 32 + sl];
                const float tpos = fmaxf(Tk, 0.0f);
                const float pneg = (Tk < 0.0f) ? Pk : 0.0f;
                const float ppos = (Tk > 0.0f) ? Pk : 0.0f;
                float sn[4];
                #pragma unroll
                for (int j = 0; j < 4; j++) {
                    const float sm = tpos * melt[j];
                    const float m  = fminf(sm, s[j]);
                    sn[j] = (s[j] - m) + pneg;
                    D[j] = fmaf(c1[j], D[j], cg[j] * (ppos + m));
                    s[j] = sn[j];
                }
                __stcs(&S4[(size_t)k * L4], make_float4(sn[0], sn[1], sn[2], sn[3]));
            }
        }
        ((float4*)g_D)[chunk * L4 + lane4] = make_float4(D[0], D[1], D[2], D[3]);
    }
    grid_sync();

    // =============== Phase E: reuse smem slab, replay, write H and Q =====
    {
        float melt[4], gi[4], c1[4], glaw[4];
        {
            float mx = w_o[0];
            #pragma unroll
            for (int j = 1; j < NH; j++) mx = fmaxf(mx, w_o[j]);
            float ssum = 0.0f;
            #pragma unroll
            for (int j = 0; j < NH; j++) ssum += expf(w_o[j] - mx);
            #pragma unroll
            for (int j = 0; j < 4; j++) {
                melt[j] = expf(w_s[b0 + j]) + 1.0f;
                gi[j]   = 1.0f / (1.0f + expf(-w_i[b0 + j]));
                const float gl = 1.0f / (1.0f + expf(-w_l[b0 + j]));
                c1[j]   = 1.0f - gl;
                glaw[j] = gl * (expf(w_o[b0 + j] - mx) / ssum);
            }
        }

        // h_start: fold over previous chunks' D (len-dependent decay)
        float hh[4] = {0, 0, 0, 0};
        {
            float c68[4], c72[4];
            #pragma unroll
            for (int j = 0; j < 4; j++) {
                const float x2  = c1[j] * c1[j];
                const float x4  = x2 * x2;
                const float x8  = x4 * x4;
                const float x16 = x8 * x8;
                const float x32 = x16 * x16;
                const float x64 = x32 * x32;
                c68[j] = x64 * x4;
                c72[j] = c68[j] * x4;
            }
            #pragma unroll 2
            for (int k = 0; k < chunk; k++) {
                const float4 D = ((const float4*)g_D)[k * L4 + lane4];
                const bool big = (k >= 14);
                hh[0] = (big ? c72[0] : c68[0]) * hh[0] + D.x;
                hh[1] = (big ? c72[1] : c68[1]) * hh[1] + D.y;
                hh[2] = (big ? c72[2] : c68[2]) * hh[2] + D.z;
                hh[3] = (big ? c72[3] : c68[3]) * hh[3] + D.w;
            }
        }

        const float4 s0v = ((const float4*)g_sstart)[chunk * L4 + lane4];
        float s[4] = {s0v.x, s0v.y, s0v.z, s0v.w};
        float4* H4 = (float4*)H + (size_t)t0 * L4 + lane4;

        for (int g0 = 0; g0 < nG; g0++) {
            #pragma unroll
            for (int u = 0; u < 4; u++) {
                const int k = g0 * 4 + u;
                const float Tk = smT[k * 32 + sl];
                const float Pk = smP[k * 32 + sl];
                const float tpos = fmaxf(Tk, 0.0f);
                const float pneg = (Tk < 0.0f) ? Pk : 0.0f;
                const float ppos = (Tk > 0.0f) ? Pk : 0.0f;
                float hn[4];
                float qa = 0.0f;
                #pragma unroll
                for (int j = 0; j < 4; j++) {
                    const float sm  = tpos * melt[j];
                    const float m   = fminf(sm, s[j]);
                    s[j] = (s[j] - m) + pneg;
                    const float u2  = fmaf(ppos + m, gi[j], hh[j]);
                    hn[j] = c1[j] * u2;            // h - q + xin
                    hh[j] = hn[j];
                    qa = fmaf(u2, glaw[j], qa);    // q*a = u2*gl*a
                }
                __stcs(&H4[(size_t)k * L4], make_float4(hn[0], hn[1], hn[2], hn[3]));

                qa += __shfl_xor_sync(0xFFFFFFFFu, qa, 1);
                qa += __shfl_xor_sync(0xFFFFFFFFu, qa, 2);
                if (bg == 0) __stcs(&Q[(t0 + k) * NS + site], qa);
            }
        }
    }
}

extern "C" void kernel_launch(void* const* d_in, const int* in_sizes, int n_in,
                              void* d_out, int out_size)
{
    const float* P   = (const float*)d_in[0];
    const float* T   = (const float*)d_in[1];
    const float* w_i = (const float*)d_in[2];
    const float* w_o = (const float*)d_in[3];
    const float* w_l = (const float*)d_in[4];
    const float* w_s = (const float*)d_in[5];

    float* Q = (float*)d_out;
    float* H = Q + (size_t)NT * NS;
    float* S = H + (size_t)NT * NS * NH;

    waternet_fused<<<NBLOCKS, BLK>>>(P, T, w_i, w_o, w_l, w_s, Q, H, S);
}